// round 14
// baseline (speedup 1.0000x reference)
#include <cuda_runtime.h>

// Problem shape (fixed): N=500000, K=81 neighbors, C=4, OUT=8.
#define KNB 81
#define CHUNK 27
#define NCHUNK 3
#define OUTC 8
#define TPB  128
#define WPB  (TPB / 32)
#define BATCH 9
#define NBAT 3
#define CAP  1000000

// Scratch (device globals: allocation-free rule)
__device__ float4 g_pts4[CAP];
__device__ ulonglong2 g_wtab[KNB * 8];          // staging for constant table
__constant__ ulonglong2 cW[KNB * 8];            // [j][c*2 + half]: packed pairs

// ---------- helpers ----------
__device__ __forceinline__ unsigned long long pack2(float a, float b) {
    unsigned long long r;
    asm("mov.b64 %0, {%1, %2};" : "=l"(r) : "f"(a), "f"(b));
    return r;
}
__device__ __forceinline__ void fma2(unsigned long long& acc,
                                     unsigned long long a, unsigned long long b) {
    asm("fma.rn.f32x2 %0, %1, %2, %0;" : "+l"(acc) : "l"(a), "l"(b));
}
__device__ __forceinline__ unsigned smem_u32(const void* p) {
    return (unsigned)__cvta_generic_to_shared(p);
}
__device__ __forceinline__ void cp4(unsigned dst, const void* src) {
    asm volatile("cp.async.ca.shared.global [%0], [%1], 4;"
                 :: "r"(dst), "l"(src) : "memory");
}

// ---------- kernel 1: pad points (+ block 0 builds weight table) ----------
__global__ void pad_points(const float* __restrict__ pts,
                           const float* __restrict__ dw,
                           const float* __restrict__ weight, int N) {
    int i = blockIdx.x * blockDim.x + threadIdx.x;
    if (i < N) {
        float x = pts[3 * i], y = pts[3 * i + 1], z = pts[3 * i + 2];
        g_pts4[i] = make_float4(x, y, z, x * x + y * y + z * z);
    }
    if (blockIdx.x == 0) {
        for (int e = threadIdx.x; e < KNB * 16; e += blockDim.x) {
            int j = e >> 4, r = e & 15, c = r >> 2, lp = r & 3;
            float dv = dw[j * 4 + c];
            const float* wp = weight + ((c * KNB + j) * OUTC + 2 * lp);
            ((unsigned long long*)g_wtab)[e] = pack2(dv * wp[0], dv * wp[1]);
        }
    }
}

// ---------- chunk body (SKIP_FIRST: chunk 0 reuses anchor) ------------------
template <bool SKIP_FIRST>
__device__ __forceinline__ void do_chunk(
    const int* __restrict__ myIdx, int chBase, float4 s,
    float c0, float msx, float msy, float msz,
    unsigned long long* acc)
{
    #pragma unroll
    for (int b = 0; b < NBAT; b++) {
        float4 pbuf[BATCH];
        #pragma unroll
        for (int u = 0; u < BATCH; u++) {
            if (SKIP_FIRST && b == 0 && u == 0)
                pbuf[0] = s;                       // anchor: no second gather
            else
                pbuf[u] = g_pts4[myIdx[b * BATCH + u]];
        }

        #pragma unroll
        for (int u = 0; u < BATCH; u++) {
            const int j = chBase + b * BATCH + u;
            float4 p = pbuf[u];
            float d = p.w + c0;                    // for p==s -> exactly 1
            d = fmaf(msx, p.x, d);
            d = fmaf(msy, p.y, d);
            d = fmaf(msz, p.z, d);

            unsigned long long f[4];
            f[0] = pack2(p.x, p.x);
            f[1] = pack2(p.y, p.y);
            f[2] = pack2(p.z, p.z);
            f[3] = pack2(d,   d);

            // Warp-uniform weights via constant port (LDC.128).
            #pragma unroll
            for (int c = 0; c < 4; c++) {
                ulonglong2 wa = cW[j * 8 + 2 * c];
                ulonglong2 wb = cW[j * 8 + 2 * c + 1];
                fma2(acc[0], f[c], wa.x);
                fma2(acc[1], f[c], wa.y);
                fma2(acc[2], f[c], wb.x);
                fma2(acc[3], f[c], wb.y);
            }
        }
    }
}

// ---------- kernel 2: fused gather + conv (warp-autonomous chunks) ---------
// Same per-thread staging rhythm as the measured optimum (27-cp4 burst ->
// drain -> gather stream), but every barrier is warp-scoped: warps never
// convoy, so one warp's staging drain overlaps other warps' compute.
__global__ __launch_bounds__(TPB, 8) void conv_main(
    const void* __restrict__ indices_raw,
    const float* __restrict__ bias,     // [8]
    float* __restrict__ out,            // [N][8]
    int N)
{
    __shared__ int sIdx[TPB * CHUNK];               // 13824 B (3456 B per warp)

    const int tid  = threadIdx.x;
    const int wid  = tid >> 5;
    const int lane = tid & 31;

    // Inline dtype detection (uniform; L2-cached).
    const unsigned long long* iq = (const unsigned long long*)indices_raw;
    bool is64 = (iq[1] < (unsigned long long)N) & (iq[2] < (unsigned long long)N)
              & (iq[3] < (unsigned long long)N) & (iq[4] < (unsigned long long)N);

    const int b0 = blockIdx.x * TPB;
    const int pw = b0 + wid * 32;          // this warp's first point
    const int n  = pw + lane;
    const bool active = (n < N);

    int* wSlice = &sIdx[wid * 32 * CHUNK];
    const unsigned wBase = smem_u32(wSlice);

    const int*       src32 = (const int*)indices_raw;
    const long long* src64 = (const long long*)indices_raw;

    float4 s = make_float4(0.f, 0.f, 0.f, 0.f);
    float c0 = 0.f, msx = 0.f, msy = 0.f, msz = 0.f;
    unsigned long long acc[4];
    #pragma unroll
    for (int lp = 0; lp < 4; lp++) acc[lp] = pack2(bias[2 * lp], bias[2 * lp + 1]);

    for (int ch = 0; ch < NCHUNK; ch++) {
        __syncwarp();   // this warp done consuming previous chunk
        // Stage this warp's 32 rows, chunk columns [ch*27, ch*27+27).
        if (is64) {
            #pragma unroll
            for (int e = lane; e < 32 * CHUNK; e += 32) {
                int p = e / CHUNK, j = e - p * CHUNK;
                if (pw + p < N)
                    wSlice[e] = (int)src64[(long long)(pw + p) * KNB + ch * CHUNK + j];
            }
        } else {
            #pragma unroll
            for (int e = lane; e < 32 * CHUNK; e += 32) {
                int p = e / CHUNK, j = e - p * CHUNK;
                if (pw + p < N)
                    cp4(wBase + 4u * e,
                        src32 + (long long)(pw + p) * KNB + ch * CHUNK + j);
            }
            asm volatile("cp.async.commit_group;\n"
                         "cp.async.wait_group 0;" ::: "memory");
        }
        __syncwarp();   // all lanes' copies drained -> slice readable

        if (active) {
            const int* myIdx = &wSlice[lane * CHUNK];
            if (ch == 0) {
                s = g_pts4[myIdx[0]];
                c0 = s.w + 1.0f;
                msx = -2.0f * s.x; msy = -2.0f * s.y; msz = -2.0f * s.z;
                do_chunk<true>(myIdx, 0, s, c0, msx, msy, msz, acc);
            } else {
                do_chunk<false>(myIdx, ch * CHUNK, s, c0, msx, msy, msz, acc);
            }
        }
    }

    if (active) {
        float2 o0 = *(float2*)&acc[0], o1 = *(float2*)&acc[1];
        float2 o2 = *(float2*)&acc[2], o3 = *(float2*)&acc[3];
        float4* op = (float4*)(out + (long long)n * OUTC);
        op[0] = make_float4(o0.x, o0.y, o1.x, o1.y);
        op[1] = make_float4(o2.x, o2.y, o3.x, o3.y);
    }
}

// ---------- launcher ----------
extern "C" void kernel_launch(void* const* d_in, const int* in_sizes, int n_in,
                              void* d_out, int out_size) {
    const float* points  = (const float*)d_in[0];   // [N,3]
    const void*  indices = d_in[1];                 // [N,81] int64 or int32
    const float* dw      = (const float*)d_in[2];   // [81,4]
    const float* weight  = (const float*)d_in[3];   // [4,81,8]
    const float* bias    = (const float*)d_in[4];   // [8]
    float* out = (float*)d_out;

    const int N = in_sizes[0] / 3;

    pad_points<<<(N + 255) / 256, 256>>>(points, dw, weight, N);

    // Combined table -> constant bank (D2D, graph-capturable).
    void* csym = nullptr; void* gsym = nullptr;
    cudaGetSymbolAddress(&csym, cW);
    cudaGetSymbolAddress(&gsym, g_wtab);
    cudaMemcpyAsync(csym, gsym, sizeof(ulonglong2) * KNB * 8,
                    cudaMemcpyDeviceToDevice, 0);

    conv_main<<<(N + TPB - 1) / TPB, TPB>>>(indices, bias, out, N);
}

// round 15
// speedup vs baseline: 1.1610x; 1.1610x over previous
#include <cuda_runtime.h>

// Problem shape (fixed): N=500000, K=81 neighbors, C=4, OUT=8.
#define KNB 81
#define CHUNK 27
#define NCHUNK 3
#define OUTC 8
#define TPB  128
#define BATCH 9
#define NBAT 3
#define CAP  1000000

// Scratch (device globals: allocation-free rule)
__device__ float4 g_pts4[CAP];
__device__ ulonglong2 g_wtab[KNB * 8];          // staging for constant table
__constant__ ulonglong2 cW[KNB * 8];            // [j][c*2 + half]: packed pairs

// ---------- helpers ----------
__device__ __forceinline__ unsigned long long pack2(float a, float b) {
    unsigned long long r;
    asm("mov.b64 %0, {%1, %2};" : "=l"(r) : "f"(a), "f"(b));
    return r;
}
__device__ __forceinline__ void fma2(unsigned long long& acc,
                                     unsigned long long a, unsigned long long b) {
    asm("fma.rn.f32x2 %0, %1, %2, %0;" : "+l"(acc) : "l"(a), "l"(b));
}
__device__ __forceinline__ unsigned smem_u32(const void* p) {
    return (unsigned)__cvta_generic_to_shared(p);
}
__device__ __forceinline__ void cp4(unsigned dst, const void* src) {
    asm volatile("cp.async.ca.shared.global [%0], [%1], 4;"
                 :: "r"(dst), "l"(src) : "memory");
}

// ---------- kernel 1: pad points (+ block 0 builds weight table) ----------
__global__ void pad_points(const float* __restrict__ pts,
                           const float* __restrict__ dw,
                           const float* __restrict__ weight, int N) {
    int i = blockIdx.x * blockDim.x + threadIdx.x;
    if (i < N) {
        float x = pts[3 * i], y = pts[3 * i + 1], z = pts[3 * i + 2];
        g_pts4[i] = make_float4(x, y, z, x * x + y * y + z * z);
    }
    if (blockIdx.x == 0) {
        for (int e = threadIdx.x; e < KNB * 16; e += blockDim.x) {
            int j = e >> 4, r = e & 15, c = r >> 2, lp = r & 3;
            float dv = dw[j * 4 + c];
            const float* wp = weight + ((c * KNB + j) * OUTC + 2 * lp);
            ((unsigned long long*)g_wtab)[e] = pack2(dv * wp[0], dv * wp[1]);
        }
    }
}

// ---------- chunk body (skipFirst is compile-time: chunk 0 reuses anchor) ---
template <bool SKIP_FIRST>
__device__ __forceinline__ void do_chunk(
    const int* __restrict__ myIdx, int chBase, float4 s,
    float c0, float msx, float msy, float msz,
    unsigned long long* acc)
{
    #pragma unroll
    for (int b = 0; b < NBAT; b++) {
        float4 pbuf[BATCH];
        #pragma unroll
        for (int u = 0; u < BATCH; u++) {
            if (SKIP_FIRST && b == 0 && u == 0)
                pbuf[0] = s;                       // anchor: no second gather
            else
                pbuf[u] = g_pts4[myIdx[b * BATCH + u]];
        }

        #pragma unroll
        for (int u = 0; u < BATCH; u++) {
            const int j = chBase + b * BATCH + u;
            float4 p = pbuf[u];
            float d = p.w + c0;                    // for p==s -> exactly 1
            d = fmaf(msx, p.x, d);
            d = fmaf(msy, p.y, d);
            d = fmaf(msz, p.z, d);

            unsigned long long f[4];
            f[0] = pack2(p.x, p.x);
            f[1] = pack2(p.y, p.y);
            f[2] = pack2(p.z, p.z);
            f[3] = pack2(d,   d);

            // Warp-uniform weights via constant port (LDC.128).
            #pragma unroll
            for (int c = 0; c < 4; c++) {
                ulonglong2 wa = cW[j * 8 + 2 * c];
                ulonglong2 wb = cW[j * 8 + 2 * c + 1];
                fma2(acc[0], f[c], wa.x);
                fma2(acc[1], f[c], wa.y);
                fma2(acc[2], f[c], wb.x);
                fma2(acc[3], f[c], wb.y);
            }
        }
    }
}

// ---------- kernel 2: fused gather + conv (measured-optimal form) ----------
// Rhythm (empirically optimal on sm_103a across 6 tested variants):
// block-wide phase-aligned 27-element cp.async staging burst -> immediate
// drain -> pure gather/LDC/FFMA2 stream. Nothing issues ahead of gathers.
__global__ __launch_bounds__(TPB, 8) void conv_main(
    const void* __restrict__ indices_raw,
    const float* __restrict__ bias,     // [8]
    float* __restrict__ out,            // [N][8]
    int N)
{
    __shared__ int sIdx[TPB * CHUNK];               // 13824 B

    const int tid = threadIdx.x;

    // Inline dtype detection (uniform; L2-cached).
    const unsigned long long* iq = (const unsigned long long*)indices_raw;
    bool is64 = (iq[1] < (unsigned long long)N) & (iq[2] < (unsigned long long)N)
              & (iq[3] < (unsigned long long)N) & (iq[4] < (unsigned long long)N);

    const int b0 = blockIdx.x * TPB;
    const int npts = min(TPB, N - b0);
    const int nelem = npts * CHUNK;
    const int n = b0 + tid;
    const bool active = (n < N);
    const unsigned sBase = smem_u32(sIdx);

    float4 s = make_float4(0.f, 0.f, 0.f, 0.f);
    float c0 = 0.f, msx = 0.f, msy = 0.f, msz = 0.f;
    unsigned long long acc[4];
    #pragma unroll
    for (int lp = 0; lp < 4; lp++) acc[lp] = pack2(bias[2 * lp], bias[2 * lp + 1]);

    for (int ch = 0; ch < NCHUNK; ch++) {
        __syncthreads();   // previous chunk fully consumed
        if (is64) {
            const long long* src = (const long long*)indices_raw;
            for (int e = tid; e < nelem; e += TPB) {
                int p = e / CHUNK, j = e - p * CHUNK;
                sIdx[e] = (int)src[(long long)(b0 + p) * KNB + ch * CHUNK + j];
            }
        } else {
            const int* src = (const int*)indices_raw;
            for (int e = tid; e < nelem; e += TPB) {
                int p = e / CHUNK, j = e - p * CHUNK;
                cp4(sBase + 4u * e,
                    src + (long long)(b0 + p) * KNB + ch * CHUNK + j);
            }
            asm volatile("cp.async.commit_group;\n"
                         "cp.async.wait_group 0;" ::: "memory");
        }
        __syncthreads();

        if (active) {
            const int* myIdx = &sIdx[tid * CHUNK];
            if (ch == 0) {
                s = g_pts4[myIdx[0]];
                c0 = s.w + 1.0f;
                msx = -2.0f * s.x; msy = -2.0f * s.y; msz = -2.0f * s.z;
                do_chunk<true>(myIdx, 0, s, c0, msx, msy, msz, acc);
            } else {
                do_chunk<false>(myIdx, ch * CHUNK, s, c0, msx, msy, msz, acc);
            }
        }
    }

    if (active) {
        float2 o0 = *(float2*)&acc[0], o1 = *(float2*)&acc[1];
        float2 o2 = *(float2*)&acc[2], o3 = *(float2*)&acc[3];
        float4* op = (float4*)(out + (long long)n * OUTC);
        op[0] = make_float4(o0.x, o0.y, o1.x, o1.y);
        op[1] = make_float4(o2.x, o2.y, o3.x, o3.y);
    }
}

// ---------- launcher ----------
extern "C" void kernel_launch(void* const* d_in, const int* in_sizes, int n_in,
                              void* d_out, int out_size) {
    const float* points  = (const float*)d_in[0];   // [N,3]
    const void*  indices = d_in[1];                 // [N,81] int64 or int32
    const float* dw      = (const float*)d_in[2];   // [81,4]
    const float* weight  = (const float*)d_in[3];   // [4,81,8]
    const float* bias    = (const float*)d_in[4];   // [8]
    float* out = (float*)d_out;

    const int N = in_sizes[0] / 3;

    pad_points<<<(N + 255) / 256, 256>>>(points, dw, weight, N);

    // Combined table -> constant bank (D2D, graph-capturable).
    void* csym = nullptr; void* gsym = nullptr;
    cudaGetSymbolAddress(&csym, cW);
    cudaGetSymbolAddress(&gsym, g_wtab);
    cudaMemcpyAsync(csym, gsym, sizeof(ulonglong2) * KNB * 8,
                    cudaMemcpyDeviceToDevice, 0);

    conv_main<<<(N + TPB - 1) / TPB, TPB>>>(indices, bias, out, N);
}